// round 15
// baseline (speedup 1.0000x reference)
#include <cuda_runtime.h>
#include <cstdint>

// Problem constants (fixed by the dataset)
#define BATCH   128
#define IN_DIM  2048
#define HID     2048
#define OUT_DIM 512
#define TSTEPS  32
#define VDECAY  0.5f
#define VTH     0.5f
#define KCHUNK  512   // reference split-K chunk (bit-exact contract from R2)

#define TB (TSTEPS * BATCH)   // 4096 batched rows

// ---------------- device scratch (no allocations allowed) ----------------
__device__ __align__(256) float g_xt[TB * IN_DIM];          // [T*B, K] transposed input
__device__ __align__(256) float g_p0[4 * TB * HID];         // layer0 chunk partials [z][m][n]
__device__ __align__(256) float g_s0all[TB * HID];          // layer0 spikes per t
__device__ __align__(256) float g_p1[4 * TB * HID];         // layer1 chunk partials
__device__ __align__(256) float g_s1all[TB * HID];          // layer1 spikes per t
__device__ __align__(256) float g_po[4 * TB * OUT_DIM];     // output-layer chunk partials
__device__ __align__(256) float g_w0t[IN_DIM * HID];        // W0 transposed: [k][n]
__device__ __align__(256) float g_w1t[HID * HID];           // W1 transposed: [k][n]
__device__ __align__(256) float g_wot[HID * OUT_DIM];       // Wo transposed: [k][n]

// packed f32x2 ops: two independent IEEE-RN operations per instruction ->
// per-element rounding identical to scalar chains (validated bit-exact in R8).
#define FMA2(accv, av, wv) \
    asm("fma.rn.f32x2 %0, %1, %2, %0;" : "+l"(accv) : "l"(av), "l"(wv))
#define CP_ASYNC16(dst_u32, src_ptr) \
    asm volatile("cp.async.cg.shared.global [%0], [%1], 16;" :: "r"(dst_u32), "l"(src_ptr))
#define CP_COMMIT() asm volatile("cp.async.commit_group;" ::: "memory")
#define CP_WAIT0()  asm volatile("cp.async.wait_group 0;" ::: "memory")

__device__ __forceinline__ uint32_t smem_u32(const void* p) {
    return (uint32_t)__cvta_generic_to_shared(p);
}
__device__ __forceinline__ float lo2(unsigned long long v) {
    return __uint_as_float((uint32_t)(v & 0xFFFFFFFFull));
}
__device__ __forceinline__ float hi2(unsigned long long v) {
    return __uint_as_float((uint32_t)(v >> 32));
}

// ---------------- transpose spike_data [B, K, T] -> [T, B, K] ----------------
__global__ void transpose_kernel(const float* __restrict__ sd) {
    __shared__ float tile[32][33];
    int b  = blockIdx.y;
    int k0 = blockIdx.x * 32;
    int tx = threadIdx.x;
    int ty = threadIdx.y;
#pragma unroll
    for (int i = 0; i < 4; i++) {
        int kl = ty + i * 8;
        tile[kl][tx] = sd[(b * IN_DIM + k0 + kl) * TSTEPS + tx];
    }
    __syncthreads();
#pragma unroll
    for (int i = 0; i < 4; i++) {
        int t = ty + i * 8;
        g_xt[(t * BATCH + b) * IN_DIM + k0 + tx] = tile[tx][t];
    }
}

// ---------------- weight transpose: in[R][C] -> out[C][R] ----------------
template <int R, int C>
__global__ void wtrans_kernel(const float* __restrict__ in, float* __restrict__ out) {
    __shared__ float tile[32][33];
    int c0 = blockIdx.x * 32;
    int r0 = blockIdx.y * 32;
    int tx = threadIdx.x;
    int ty = threadIdx.y;
#pragma unroll
    for (int i = 0; i < 4; i++)
        tile[ty + i * 8][tx] = in[(size_t)(r0 + ty + i * 8) * C + c0 + tx];
    __syncthreads();
#pragma unroll
    for (int i = 0; i < 4; i++)
        out[(size_t)(c0 + ty + i * 8) * R + r0 + tx] = tile[tx][ty + i * 8];
}

// ---------------- LIF scan over time (folds 4 chunk partials) ----------------
// g = ((p0+p1)+p2)+p3 left-assoc (== in-kernel fold since 0+c0 rounds to c0);
// then v = (0.5*v*(1-s) + g) + bias ; s = (v > VTH). Bit-exact contract.
template <int N>
__global__ void lif_scan_kernel(const float* __restrict__ pin,   // [4][T*B*N]
                                float* __restrict__ sall,        // [T, B*N]
                                const float* __restrict__ v0in,
                                const float* __restrict__ s0in,
                                const float* __restrict__ bias) {
    int idx = blockIdx.x * blockDim.x + threadIdx.x;
    if (idx >= BATCH * N) return;
    const size_t PL = (size_t)TB * N;    // plane stride
    float vv = v0in[idx];
    float ss = s0in[idx];
    float bb = bias[idx % N];
#pragma unroll
    for (int t = 0; t < TSTEPS; t++) {
        size_t o = (size_t)t * BATCH * N + idx;
        float g = __fadd_rn(__fadd_rn(__fadd_rn(pin[o], pin[PL + o]), pin[2 * PL + o]),
                            pin[3 * PL + o]);
        float decay = __fmul_rn(__fmul_rn(VDECAY, vv), __fadd_rn(1.0f, -ss));
        vv = __fadd_rn(__fadd_rn(decay, g), bb);
        ss = (vv > VTH) ? 1.0f : 0.0f;
        sall[o] = ss;
    }
}

// ---------------- output-layer LIF scan: fold partials + spike counts ----------------
__global__ void lifo_scan_kernel(const float* __restrict__ pin,  // [4][T*B*OUT]
                                 const float* __restrict__ v0in,
                                 const float* __restrict__ s0in,
                                 const float* __restrict__ bias,
                                 float* __restrict__ out) {
    int idx = blockIdx.x * blockDim.x + threadIdx.x;
    if (idx >= BATCH * OUT_DIM) return;
    const size_t PL = (size_t)TB * OUT_DIM;
    float vv = v0in[idx];
    float ss = s0in[idx];
    float bb = bias[idx % OUT_DIM];
    float acc = 0.0f;
#pragma unroll
    for (int t = 0; t < TSTEPS; t++) {
        size_t o = (size_t)t * BATCH * OUT_DIM + idx;
        float g = __fadd_rn(__fadd_rn(__fadd_rn(pin[o], pin[PL + o]), pin[2 * PL + o]),
                            pin[3 * PL + o]);
        float decay = __fmul_rn(__fmul_rn(VDECAY, vv), __fadd_rn(1.0f, -ss));
        vv = __fadd_rn(__fadd_rn(decay, g), bb);
        ss = (vv > VTH) ? 1.0f : 0.0f;
        acc += ss;
    }
    out[idx] = acc;
}

// ---------------- split-K chunk GEMM: f32x2, TM8xTN8, cp.async W, dup-X smem ----------------
// Partial[z][m][n] = sum over k in chunk z of X[m][k]*Wt[k][n], serial in-order
// FMA per element (bit-exact chunk chain from R2 contract).
// X staged LDG->reg->STS.64 as DUPLICATED (x,x) pairs: the packed a-operand is
// read directly (broadcast LDS.128), eliminating all inner-loop mov-packing.
// W arrives via cp.async from the k-major transposed copy.
// BM=64, BN=128, 128 threads; thread tile 8x8.
template <int M, int N, int KTOT>
__global__ __launch_bounds__(128, 4) void gemm_kernel(
    const float* __restrict__ X,
    const float* __restrict__ Wt,      // [KTOT][N] k-major
    float* __restrict__ part)
{
    constexpr int BK  = 16;
    constexpr int BM  = 64;
    constexpr int BN  = 128;
    constexpr int NT  = KCHUNK / BK;       // 32 tiles in this CTA's chunk
    constexpr int XLD = BM * BK / 128;     // 8
    constexpr int XPITCH = 2 * BM + 4;     // 132 floats (duplicated pairs)
    constexpr int WPITCH = BN + 4;         // 132 floats

    __shared__ __align__(16) float Xs[2][BK][XPITCH];
    __shared__ __align__(16) float Ws[2][BK][WPITCH];

    const int tid = threadIdx.x;
    const int m0 = blockIdx.y * BM;
    const int n0 = blockIdx.x * BN;
    const int kbase = blockIdx.z * KCHUNK;

    const int lk = tid % BK;
    const int lr = tid / BK;               // 0..7
    const float* Xp = X + (size_t)(m0 + lr) * KTOT + kbase + lk;

    // cp.async W mapping: 512 x 16B chunks per tile; thread does 4.
    const int wrow0 = tid / 32;            // rows wrow0, +4, +8, +12
    const int wc16  = tid % 32;
    const float* Wp = Wt + (size_t)(kbase + wrow0) * N + n0 + wc16 * 4;

    const int tx = tid % 16;
    const int ty = tid / 16;               // 0..7

    float xr[XLD];
    unsigned long long acc[8][4];
#pragma unroll
    for (int i = 0; i < 8; i++)
#pragma unroll
        for (int j = 0; j < 4; j++) acc[i][j] = 0ull;

    // prologue: W tile0 via cp.async ; X tile0 regs->smem (duplicated) ; X tile1 regs
    {
        uint32_t wdst = smem_u32(&Ws[0][wrow0][wc16 * 4]);
#pragma unroll
        for (int i = 0; i < 4; i++)
            CP_ASYNC16(wdst + i * 4 * WPITCH * 4, Wp + (size_t)i * 4 * N);
        CP_COMMIT();
    }
#pragma unroll
    for (int i = 0; i < XLD; i++) xr[i] = Xp[(size_t)i * 8 * KTOT];
#pragma unroll
    for (int i = 0; i < XLD; i++)
        *reinterpret_cast<float2*>(&Xs[0][lk][2 * (lr + i * 8)]) = make_float2(xr[i], xr[i]);
#pragma unroll
    for (int i = 0; i < XLD; i++) xr[i] = Xp[(size_t)i * 8 * KTOT + BK];
    CP_WAIT0();
    __syncthreads();

    for (int t = 0; t < NT; t++) {
        const int cur = t & 1;
        const int nxt = cur ^ 1;
        if (t + 1 < NT) {
            // W tile t+1 -> free buffer via cp.async (in flight during compute)
            uint32_t wdst = smem_u32(&Ws[nxt][wrow0][wc16 * 4]);
            const float* wsrc = Wp + (size_t)(t + 1) * BK * N;
#pragma unroll
            for (int i = 0; i < 4; i++)
                CP_ASYNC16(wdst + i * 4 * WPITCH * 4, wsrc + (size_t)i * 4 * N);
            CP_COMMIT();
            // X tile t+1 regs -> free buffer (duplicated pairs)
#pragma unroll
            for (int i = 0; i < XLD; i++)
                *reinterpret_cast<float2*>(&Xs[nxt][lk][2 * (lr + i * 8)]) =
                    make_float2(xr[i], xr[i]);
        }
        if (t + 2 < NT) {
#pragma unroll
            for (int i = 0; i < XLD; i++) xr[i] = Xp[(size_t)i * 8 * KTOT + (t + 2) * BK];
        }

#pragma unroll
        for (int kk = 0; kk < BK; kk++) {
            // duplicated pairs: rows ty*4..+3 at [ty*8..ty*8+7], rows 32+ty*4..+3 at [64+ty*8..]
            ulonglong2 xa0 = *reinterpret_cast<const ulonglong2*>(&Xs[cur][kk][ty * 8]);
            ulonglong2 xa1 = *reinterpret_cast<const ulonglong2*>(&Xs[cur][kk][ty * 8 + 4]);
            ulonglong2 xb0 = *reinterpret_cast<const ulonglong2*>(&Xs[cur][kk][64 + ty * 8]);
            ulonglong2 xb1 = *reinterpret_cast<const ulonglong2*>(&Xs[cur][kk][64 + ty * 8 + 4]);
            ulonglong2 wA = *reinterpret_cast<const ulonglong2*>(&Ws[cur][kk][tx * 4]);
            ulonglong2 wB = *reinterpret_cast<const ulonglong2*>(&Ws[cur][kk][64 + tx * 4]);
            FMA2(acc[0][0], xa0.x, wA.x); FMA2(acc[0][1], xa0.x, wA.y);
            FMA2(acc[0][2], xa0.x, wB.x); FMA2(acc[0][3], xa0.x, wB.y);
            FMA2(acc[1][0], xa0.y, wA.x); FMA2(acc[1][1], xa0.y, wA.y);
            FMA2(acc[1][2], xa0.y, wB.x); FMA2(acc[1][3], xa0.y, wB.y);
            FMA2(acc[2][0], xa1.x, wA.x); FMA2(acc[2][1], xa1.x, wA.y);
            FMA2(acc[2][2], xa1.x, wB.x); FMA2(acc[2][3], xa1.x, wB.y);
            FMA2(acc[3][0], xa1.y, wA.x); FMA2(acc[3][1], xa1.y, wA.y);
            FMA2(acc[3][2], xa1.y, wB.x); FMA2(acc[3][3], xa1.y, wB.y);
            FMA2(acc[4][0], xb0.x, wA.x); FMA2(acc[4][1], xb0.x, wA.y);
            FMA2(acc[4][2], xb0.x, wB.x); FMA2(acc[4][3], xb0.x, wB.y);
            FMA2(acc[5][0], xb0.y, wA.x); FMA2(acc[5][1], xb0.y, wA.y);
            FMA2(acc[5][2], xb0.y, wB.x); FMA2(acc[5][3], xb0.y, wB.y);
            FMA2(acc[6][0], xb1.x, wA.x); FMA2(acc[6][1], xb1.x, wA.y);
            FMA2(acc[6][2], xb1.x, wB.x); FMA2(acc[6][3], xb1.x, wB.y);
            FMA2(acc[7][0], xb1.y, wA.x); FMA2(acc[7][1], xb1.y, wA.y);
            FMA2(acc[7][2], xb1.y, wB.x); FMA2(acc[7][3], xb1.y, wB.y);
        }

        if (t + 1 < NT) CP_WAIT0();
        __syncthreads();
    }

    // epilogue: store this chunk's raw partial sums [z][m][n]
    float* base = part + (size_t)blockIdx.z * M * N;
#pragma unroll
    for (int i = 0; i < 8; i++) {
        int m = (i < 4) ? (m0 + ty * 4 + i) : (m0 + 32 + ty * 4 + (i - 4));
        float* orow = base + (size_t)m * N + n0;
#pragma unroll
        for (int h = 0; h < 2; h++) {   // h=0 -> cols tx*4 ; h=1 -> 64+tx*4
            float4 f4;
            f4.x = lo2(acc[i][2 * h]);
            f4.y = hi2(acc[i][2 * h]);
            f4.z = lo2(acc[i][2 * h + 1]);
            f4.w = hi2(acc[i][2 * h + 1]);
            *reinterpret_cast<float4*>(orow + h * 64 + tx * 4) = f4;
        }
    }
}

// ---------------- launcher ----------------
extern "C" void kernel_launch(void* const* d_in, const int* in_sizes, int n_in,
                              void* d_out, int out_size) {
    (void)in_sizes; (void)n_in; (void)out_size;
    const float* sd  = (const float*)d_in[0];
    const float* h0v = (const float*)d_in[1];
    const float* h0s = (const float*)d_in[2];
    const float* h1v = (const float*)d_in[3];
    const float* h1s = (const float*)d_in[4];
    const float* ov  = (const float*)d_in[5];
    const float* os  = (const float*)d_in[6];
    const float* W0  = (const float*)d_in[7];
    const float* b0  = (const float*)d_in[8];
    const float* W1  = (const float*)d_in[9];
    const float* b1  = (const float*)d_in[10];
    const float* Wo  = (const float*)d_in[11];
    const float* bo  = (const float*)d_in[12];
    float* out = (float*)d_out;

    float *xt, *p0, *s0all, *p1, *s1all, *po, *w0t, *w1t, *wot;
    cudaGetSymbolAddress((void**)&xt,    g_xt);
    cudaGetSymbolAddress((void**)&p0,    g_p0);
    cudaGetSymbolAddress((void**)&s0all, g_s0all);
    cudaGetSymbolAddress((void**)&p1,    g_p1);
    cudaGetSymbolAddress((void**)&s1all, g_s1all);
    cudaGetSymbolAddress((void**)&po,    g_po);
    cudaGetSymbolAddress((void**)&w0t,   g_w0t);
    cudaGetSymbolAddress((void**)&w1t,   g_w1t);
    cudaGetSymbolAddress((void**)&wot,   g_wot);

    // 0) weight transposes (k-major for cp.async)
    {
        dim3 tb(32, 8);
        dim3 g0(IN_DIM / 32, HID / 32);
        wtrans_kernel<HID, IN_DIM><<<g0, tb>>>(W0, w0t);
        dim3 g1(HID / 32, HID / 32);
        wtrans_kernel<HID, HID><<<g1, tb>>>(W1, w1t);
        dim3 g2(HID / 32, OUT_DIM / 32);
        wtrans_kernel<OUT_DIM, HID><<<g2, tb>>>(Wo, wot);
    }

    // 1) transpose input [B,K,T] -> [T,B,K]
    {
        dim3 tb(32, 8);
        dim3 tg(IN_DIM / 32, BATCH);
        transpose_kernel<<<tg, tb>>>(sd);
    }

    // 2) layer0 GEMM (split-K chunks, M = T*B = 4096)
    {
        dim3 grid(HID / 128, TB / 64, 4);   // (16, 64, 4) = 4096 CTAs
        gemm_kernel<TB, HID, IN_DIM><<<grid, 128>>>(xt, w0t, p0);
    }

    // 3) layer0 LIF scan (folds partials)
    lif_scan_kernel<HID><<<(BATCH * HID + 255) / 256, 256>>>(p0, s0all, h0v, h0s, b0);

    // 4) layer1 GEMM
    {
        dim3 grid(HID / 128, TB / 64, 4);
        gemm_kernel<TB, HID, HID><<<grid, 128>>>(s0all, w1t, p1);
    }

    // 5) layer1 LIF scan
    lif_scan_kernel<HID><<<(BATCH * HID + 255) / 256, 256>>>(p1, s1all, h1v, h1s, b1);

    // 6) output-layer GEMM
    {
        dim3 grid(OUT_DIM / 128, TB / 64, 4);   // (4, 64, 4) = 1024 CTAs
        gemm_kernel<TB, OUT_DIM, HID><<<grid, 128>>>(s1all, wot, po);
    }

    // 7) output LIF scan + spike-count accumulation
    lifo_scan_kernel<<<(BATCH * OUT_DIM + 255) / 256, 256>>>(po, ov, os, bo, out);
}

// round 16
// speedup vs baseline: 1.2928x; 1.2928x over previous
#include <cuda_runtime.h>
#include <cstdint>

// Problem constants (fixed by the dataset)
#define BATCH   128
#define IN_DIM  2048
#define HID     2048
#define OUT_DIM 512
#define TSTEPS  32
#define VDECAY  0.5f
#define VTH     0.5f
#define KCHUNK  512   // reference split-K chunk (bit-exact contract from R2)

#define TB (TSTEPS * BATCH)   // 4096 batched rows

// ---------------- device scratch (no allocations allowed) ----------------
__device__ float g_xt[TB * IN_DIM];          // [T*B, K] transposed input
__device__ float g_p0[4 * TB * HID];         // layer0 chunk partials [z][T*B, H]
__device__ float g_s0all[TB * HID];          // layer0 spikes per t
__device__ float g_p1[4 * TB * HID];         // layer1 chunk partials
__device__ float g_s1all[TB * HID];          // layer1 spikes per t
__device__ float g_po[4 * TB * OUT_DIM];     // output-layer chunk partials
__device__ float g_w0t[IN_DIM * HID];        // W0 transposed: [k][n]
__device__ float g_w1t[HID * HID];           // W1 transposed: [k][n]
__device__ float g_wot[HID * OUT_DIM];       // Wo transposed: [k][n]

// packed f32x2 ops: two independent IEEE-RN operations per instruction ->
// per-element rounding identical to scalar chains (validated bit-exact in R8).
#define FMA2(accv, av, wv) \
    asm("fma.rn.f32x2 %0, %1, %2, %0;" : "+l"(accv) : "l"(av), "l"(wv))
#define DUP2(dst, fval) \
    asm("mov.b64 %0, {%1, %1};" : "=l"(dst) : "r"(__float_as_uint(fval)))
#define CP_ASYNC16(dst_u32, src_ptr) \
    asm volatile("cp.async.cg.shared.global [%0], [%1], 16;" :: "r"(dst_u32), "l"(src_ptr))
#define CP_COMMIT() asm volatile("cp.async.commit_group;" ::: "memory")
#define CP_WAIT0()  asm volatile("cp.async.wait_group 0;" ::: "memory")

__device__ __forceinline__ uint32_t smem_u32(const void* p) {
    return (uint32_t)__cvta_generic_to_shared(p);
}

// ---------------- transpose spike_data [B, K, T] -> [T, B, K] ----------------
__global__ void transpose_kernel(const float* __restrict__ sd) {
    __shared__ float tile[32][33];
    int b  = blockIdx.y;
    int k0 = blockIdx.x * 32;
    int tx = threadIdx.x;
    int ty = threadIdx.y;
#pragma unroll
    for (int i = 0; i < 4; i++) {
        int kl = ty + i * 8;
        tile[kl][tx] = sd[(b * IN_DIM + k0 + kl) * TSTEPS + tx];
    }
    __syncthreads();
#pragma unroll
    for (int i = 0; i < 4; i++) {
        int t = ty + i * 8;
        g_xt[(t * BATCH + b) * IN_DIM + k0 + tx] = tile[tx][t];
    }
}

// ---------------- weight transpose: in[R][C] -> out[C][R] ----------------
template <int R, int C>
__global__ void wtrans_kernel(const float* __restrict__ in, float* __restrict__ out) {
    __shared__ float tile[32][33];
    int c0 = blockIdx.x * 32;
    int r0 = blockIdx.y * 32;
    int tx = threadIdx.x;
    int ty = threadIdx.y;
#pragma unroll
    for (int i = 0; i < 4; i++)
        tile[ty + i * 8][tx] = in[(size_t)(r0 + ty + i * 8) * C + c0 + tx];
    __syncthreads();
#pragma unroll
    for (int i = 0; i < 4; i++)
        out[(size_t)(c0 + ty + i * 8) * R + r0 + tx] = tile[tx][ty + i * 8];
}

// ---------------- LIF scan over time (folds 4 chunk partials) ----------------
// g = ((p0+p1)+p2)+p3 left-assoc (== in-kernel fold since 0+c0 rounds to c0);
// then v = (0.5*v*(1-s) + g) + bias ; s = (v > VTH). Bit-exact contract.
template <int N>
__global__ void lif_scan_kernel(const float* __restrict__ pin,   // [4][T*B*N]
                                float* __restrict__ sall,        // [T, B*N]
                                const float* __restrict__ v0in,
                                const float* __restrict__ s0in,
                                const float* __restrict__ bias) {
    int idx = blockIdx.x * blockDim.x + threadIdx.x;
    if (idx >= BATCH * N) return;
    const size_t PL = (size_t)TB * N;    // plane stride
    float vv = v0in[idx];
    float ss = s0in[idx];
    float bb = bias[idx % N];
#pragma unroll
    for (int t = 0; t < TSTEPS; t++) {
        size_t o = (size_t)t * BATCH * N + idx;
        float g = __fadd_rn(__fadd_rn(__fadd_rn(pin[o], pin[PL + o]), pin[2 * PL + o]),
                            pin[3 * PL + o]);
        float decay = __fmul_rn(__fmul_rn(VDECAY, vv), __fadd_rn(1.0f, -ss));
        vv = __fadd_rn(__fadd_rn(decay, g), bb);
        ss = (vv > VTH) ? 1.0f : 0.0f;
        sall[o] = ss;
    }
}

// ---------------- output-layer LIF scan: fold partials + spike counts ----------------
__global__ void lifo_scan_kernel(const float* __restrict__ pin,  // [4][T*B*OUT]
                                 const float* __restrict__ v0in,
                                 const float* __restrict__ s0in,
                                 const float* __restrict__ bias,
                                 float* __restrict__ out) {
    int idx = blockIdx.x * blockDim.x + threadIdx.x;
    if (idx >= BATCH * OUT_DIM) return;
    const size_t PL = (size_t)TB * OUT_DIM;
    float vv = v0in[idx];
    float ss = s0in[idx];
    float bb = bias[idx % OUT_DIM];
    float acc = 0.0f;
#pragma unroll
    for (int t = 0; t < TSTEPS; t++) {
        size_t o = (size_t)t * BATCH * OUT_DIM + idx;
        float g = __fadd_rn(__fadd_rn(__fadd_rn(pin[o], pin[PL + o]), pin[2 * PL + o]),
                            pin[3 * PL + o]);
        float decay = __fmul_rn(__fmul_rn(VDECAY, vv), __fadd_rn(1.0f, -ss));
        vv = __fadd_rn(__fadd_rn(decay, g), bb);
        ss = (vv > VTH) ? 1.0f : 0.0f;
        acc += ss;
    }
    out[idx] = acc;
}

// ---------------- split-K chunk GEMM, packed f32x2, TM8xTN8, cp.async W ----------------
// Partial[z][m][n] = sum over k in [z*512, z*512+512) of X[m][k]*Wt[k][n],
// serial in-order FMA per element (bit-exact chunk chain from R2 contract).
// W arrives via cp.async from the k-major transposed copy (no staging regs/STS).
// BM=64, BN=128, 128 threads; thread tile 8x8.
template <int M, int N, int KTOT>
__global__ __launch_bounds__(128, 4) void gemm_kernel(
    const float* __restrict__ X,
    const float* __restrict__ Wt,      // [KTOT][N] k-major
    float* __restrict__ part)
{
    constexpr int BK  = 16;
    constexpr int BM  = 64;
    constexpr int BN  = 128;
    constexpr int NT  = KCHUNK / BK;       // 32 tiles in this CTA's chunk
    constexpr int XLD = BM * BK / 128;     // 8
    constexpr int WPITCH = BN + 4;         // 132 floats per smem W row

    __shared__ __align__(16) float Xs[2][BK][BM + 4];
    __shared__ __align__(16) float Ws[2][BK][WPITCH];

    const int tid = threadIdx.x;
    const int m0 = blockIdx.y * BM;
    const int n0 = blockIdx.x * BN;
    const int kbase = blockIdx.z * KCHUNK;

    const int lk = tid % BK;
    const int lr = tid / BK;               // 0..7
    const float* Xp = X + (size_t)(m0 + lr) * KTOT + kbase + lk;

    // cp.async W mapping: 512 x 16B chunks per tile; thread does 4.
    const int wrow0 = tid / 32;            // rows wrow0, wrow0+4, +8, +12
    const int wc16  = tid % 32;
    const float* Wp = Wt + (size_t)(kbase + wrow0) * N + n0 + wc16 * 4;

    const int tx = tid % 16;
    const int ty = tid / 16;               // 0..7

    float xr[XLD];
    unsigned long long acc[8][4];
#pragma unroll
    for (int i = 0; i < 8; i++)
#pragma unroll
        for (int j = 0; j < 4; j++) acc[i][j] = 0ull;

    // prologue: W tile0 via cp.async ; X tile0 regs->smem ; X tile1 regs
    {
        uint32_t wdst = smem_u32(&Ws[0][wrow0][wc16 * 4]);
#pragma unroll
        for (int i = 0; i < 4; i++)
            CP_ASYNC16(wdst + i * 4 * WPITCH * 4, Wp + (size_t)i * 4 * N);
        CP_COMMIT();
    }
#pragma unroll
    for (int i = 0; i < XLD; i++) xr[i] = Xp[(size_t)i * 8 * KTOT];
#pragma unroll
    for (int i = 0; i < XLD; i++) Xs[0][lk][lr + i * 8] = xr[i];
#pragma unroll
    for (int i = 0; i < XLD; i++) xr[i] = Xp[(size_t)i * 8 * KTOT + BK];
    CP_WAIT0();
    __syncthreads();

    for (int t = 0; t < NT; t++) {
        const int cur = t & 1;
        const int nxt = cur ^ 1;
        if (t + 1 < NT) {
            // W tile t+1 -> free buffer via cp.async (in flight during compute)
            uint32_t wdst = smem_u32(&Ws[nxt][wrow0][wc16 * 4]);
            const float* wsrc = Wp + (size_t)(t + 1) * BK * N;
#pragma unroll
            for (int i = 0; i < 4; i++)
                CP_ASYNC16(wdst + i * 4 * WPITCH * 4, wsrc + (size_t)i * 4 * N);
            CP_COMMIT();
            // X tile t+1 regs -> free buffer
#pragma unroll
            for (int i = 0; i < XLD; i++) Xs[nxt][lk][lr + i * 8] = xr[i];
        }
        if (t + 2 < NT) {
#pragma unroll
            for (int i = 0; i < XLD; i++) xr[i] = Xp[(size_t)i * 8 * KTOT + (t + 2) * BK];
        }

#pragma unroll
        for (int kk = 0; kk < BK; kk++) {
            float4 xa = *reinterpret_cast<const float4*>(&Xs[cur][kk][ty * 4]);
            float4 xb = *reinterpret_cast<const float4*>(&Xs[cur][kk][32 + ty * 4]);
            ulonglong2 wA = *reinterpret_cast<const ulonglong2*>(&Ws[cur][kk][tx * 4]);
            ulonglong2 wB = *reinterpret_cast<const ulonglong2*>(&Ws[cur][kk][64 + tx * 4]);
            unsigned long long aa[8];
            DUP2(aa[0], xa.x); DUP2(aa[1], xa.y); DUP2(aa[2], xa.z); DUP2(aa[3], xa.w);
            DUP2(aa[4], xb.x); DUP2(aa[5], xb.y); DUP2(aa[6], xb.z); DUP2(aa[7], xb.w);
#pragma unroll
            for (int i = 0; i < 8; i++) {
                FMA2(acc[i][0], aa[i], wA.x);
                FMA2(acc[i][1], aa[i], wA.y);
                FMA2(acc[i][2], aa[i], wB.x);
                FMA2(acc[i][3], aa[i], wB.y);
            }
        }

        if (t + 1 < NT) CP_WAIT0();
        __syncthreads();
    }

    // epilogue: store this chunk's raw partial sums
    float* base = part + (size_t)blockIdx.z * M * N;
#pragma unroll
    for (int i = 0; i < 8; i++) {
        int m = (i < 4) ? (m0 + ty * 4 + i) : (m0 + 32 + ty * 4 + (i - 4));
        float* orow = base + (size_t)m * N + n0;
#pragma unroll
        for (int h = 0; h < 2; h++) {   // h=0 -> cols tx*4 ; h=1 -> 64+tx*4
            float4 f4;
            f4.x = __uint_as_float((uint32_t)(acc[i][2 * h] & 0xFFFFFFFFull));
            f4.y = __uint_as_float((uint32_t)(acc[i][2 * h] >> 32));
            f4.z = __uint_as_float((uint32_t)(acc[i][2 * h + 1] & 0xFFFFFFFFull));
            f4.w = __uint_as_float((uint32_t)(acc[i][2 * h + 1] >> 32));
            *reinterpret_cast<float4*>(orow + h * 64 + tx * 4) = f4;
        }
    }
}

// ---------------- launcher ----------------
extern "C" void kernel_launch(void* const* d_in, const int* in_sizes, int n_in,
                              void* d_out, int out_size) {
    (void)in_sizes; (void)n_in; (void)out_size;
    const float* sd  = (const float*)d_in[0];
    const float* h0v = (const float*)d_in[1];
    const float* h0s = (const float*)d_in[2];
    const float* h1v = (const float*)d_in[3];
    const float* h1s = (const float*)d_in[4];
    const float* ov  = (const float*)d_in[5];
    const float* os  = (const float*)d_in[6];
    const float* W0  = (const float*)d_in[7];
    const float* b0  = (const float*)d_in[8];
    const float* W1  = (const float*)d_in[9];
    const float* b1  = (const float*)d_in[10];
    const float* Wo  = (const float*)d_in[11];
    const float* bo  = (const float*)d_in[12];
    float* out = (float*)d_out;

    float *xt, *p0, *s0all, *p1, *s1all, *po, *w0t, *w1t, *wot;
    cudaGetSymbolAddress((void**)&xt,    g_xt);
    cudaGetSymbolAddress((void**)&p0,    g_p0);
    cudaGetSymbolAddress((void**)&s0all, g_s0all);
    cudaGetSymbolAddress((void**)&p1,    g_p1);
    cudaGetSymbolAddress((void**)&s1all, g_s1all);
    cudaGetSymbolAddress((void**)&po,    g_po);
    cudaGetSymbolAddress((void**)&w0t,   g_w0t);
    cudaGetSymbolAddress((void**)&w1t,   g_w1t);
    cudaGetSymbolAddress((void**)&wot,   g_wot);

    // 0) weight transposes (k-major for cp.async)
    {
        dim3 tb(32, 8);
        dim3 g0(IN_DIM / 32, HID / 32);
        wtrans_kernel<HID, IN_DIM><<<g0, tb>>>(W0, w0t);
        dim3 g1(HID / 32, HID / 32);
        wtrans_kernel<HID, HID><<<g1, tb>>>(W1, w1t);
        dim3 g2(HID / 32, OUT_DIM / 32);
        wtrans_kernel<OUT_DIM, HID><<<g2, tb>>>(Wo, wot);
    }

    // 1) transpose input [B,K,T] -> [T,B,K]
    {
        dim3 tb(32, 8);
        dim3 tg(IN_DIM / 32, BATCH);
        transpose_kernel<<<tg, tb>>>(sd);
    }

    // 2) layer0 GEMM (split-K chunks, M = T*B = 4096)
    {
        dim3 grid(HID / 128, TB / 64, 4);   // (16, 64, 4) = 4096 CTAs
        gemm_kernel<TB, HID, IN_DIM><<<grid, 128>>>(xt, w0t, p0);
    }

    // 3) layer0 LIF scan (folds partials)
    lif_scan_kernel<HID><<<(BATCH * HID + 255) / 256, 256>>>(p0, s0all, h0v, h0s, b0);

    // 4) layer1 GEMM
    {
        dim3 grid(HID / 128, TB / 64, 4);
        gemm_kernel<TB, HID, HID><<<grid, 128>>>(s0all, w1t, p1);
    }

    // 5) layer1 LIF scan
    lif_scan_kernel<HID><<<(BATCH * HID + 255) / 256, 256>>>(p1, s1all, h1v, h1s, b1);

    // 6) output-layer GEMM
    {
        dim3 grid(OUT_DIM / 128, TB / 64, 4);   // (4, 64, 4) = 1024 CTAs
        gemm_kernel<TB, OUT_DIM, HID><<<grid, 128>>>(s1all, wot, po);
    }

    // 7) output LIF scan + spike-count accumulation
    lifo_scan_kernel<<<(BATCH * OUT_DIM + 255) / 256, 256>>>(po, ov, os, bo, out);
}